// round 4
// baseline (speedup 1.0000x reference)
#include <cuda_runtime.h>
#include <cuda_bf16.h>
#include <math.h>
#include <stdint.h>

// ---------------- problem constants ----------------
#define C_N   1024
#define C_K   16
#define C_D   512
#define C_H   8
#define C_FF  2048
#define C_MA  64
#define C_ES  64
#define C_E   (C_N * C_K)      // 16384
#define C_EPS 1e-6f

typedef __nv_bfloat16 bf16;

// ---------------- fp32 scratch ----------------
__device__ float g_TV  [3][C_N][C_D];
__device__ float g_MSG [3][C_E][C_D];
__device__ float g_w   [C_E][3*C_D];
__device__ float g_PV  [3][C_E][C_D];
__device__ float g_araw[C_E][C_MA];
__device__ float g_attr[C_E][C_H];
__device__ float g_att [C_E][C_H];
__device__ float g_XP  [3][C_N][C_D];
__device__ float g_X1  [3][C_N][C_D];
__device__ float g_Y   [3][C_N][C_FF];
__device__ float g_DV  [3][C_N][C_FF];
__device__ float g_Y3  [3][C_N][C_D];

// ---------------- bf16 hi/lo pairs (GEMM operands) ----------------
__device__ __align__(128) bf16 g_Tb_h [3][C_N][C_D],        g_Tb_l [3][C_N][C_D];
__device__ __align__(128) bf16 g_Mb_h [3][C_E][C_D],        g_Mb_l [3][C_E][C_D];
__device__ __align__(128) bf16 g_pscb_h[C_E][C_D],          g_pscb_l[C_E][C_D];
__device__ __align__(128) bf16 g_Zb_h [3][C_N][C_H][C_D],   g_Zb_l [3][C_N][C_H][C_D];
__device__ __align__(128) bf16 g_OUTb_h[3][C_N][C_D],       g_OUTb_l[3][C_N][C_D];
__device__ __align__(128) bf16 g_X1b_h[3][C_N][C_D],        g_X1b_l[3][C_N][C_D];
__device__ __align__(128) bf16 g_Yb_h [3][C_N][C_FF],       g_Yb_l [3][C_N][C_FF];
__device__ __align__(128) bf16 g_Y2b_h[3][C_N][C_FF],       g_Y2b_l[3][C_N][C_FF];
// weights
__device__ __align__(128) bf16 g_Wsrc_h[C_D*C_D],  g_Wsrc_l[C_D*C_D];
__device__ __align__(128) bf16 g_Wdst_h[C_D*C_D],  g_Wdst_l[C_D*C_D];
__device__ __align__(128) bf16 g_Wa_h  [C_MA*C_D], g_Wa_l  [C_MA*C_D];
__device__ __align__(128) bf16 g_Wv_h  [C_D*C_D],  g_Wv_l  [C_D*C_D];
__device__ __align__(128) bf16 g_Wp_h  [C_D*C_D],  g_Wp_l  [C_D*C_D];
__device__ __align__(128) bf16 g_Wf1_h [C_FF*C_D], g_Wf1_l [C_FF*C_D];
__device__ __align__(128) bf16 g_Wfd_h [C_FF*C_FF],g_Wfd_l [C_FF*C_FF];
__device__ __align__(128) bf16 g_Wf2_h [C_D*C_FF], g_Wf2_l [C_D*C_FF];

// ---------------- helpers ----------------
__device__ __forceinline__ void bsplit(float v, bf16* H, bf16* L, long i) {
    bf16 h = __float2bfloat16_rn(v);
    H[i] = h;
    L[i] = __float2bfloat16_rn(v - __bfloat162float(h));
}
__device__ __forceinline__ uint32_t s2u(const void* p) {
    uint32_t a;
    asm("{ .reg .u64 t; cvta.to.shared.u64 t, %1; cvt.u32.u64 %0, t; }" : "=r"(a) : "l"(p));
    return a;
}
__device__ __forceinline__ void mma_bf16(float* c, const uint32_t* a, const uint32_t* b) {
    asm volatile("mma.sync.aligned.m16n8k16.row.col.f32.bf16.bf16.f32 "
                 "{%0,%1,%2,%3},{%4,%5,%6,%7},{%8,%9},{%0,%1,%2,%3};"
                 : "+f"(c[0]), "+f"(c[1]), "+f"(c[2]), "+f"(c[3])
                 : "r"(a[0]), "r"(a[1]), "r"(a[2]), "r"(a[3]), "r"(b[0]), "r"(b[1]));
}
#define CPA(d, s) asm volatile("cp.async.cg.shared.global [%0], [%1], 16;" :: "r"(d), "l"(s) : "memory")
#define CPC()     asm volatile("cp.async.commit_group;" ::: "memory")
#define CPW(n)    asm volatile("cp.async.wait_group %0;" :: "n"(n) : "memory")

// ============ bf16-pair NT GEMM: C[m,n] = sum_k A[m,k]*B[n,k] (+Add) ============
// inputs pre-split hi/lo; 3 HMMA passes (hh + hl + lh). M%128==0, N%BN==0, K%32==0.
template<int BN>
__global__ void __launch_bounds__(256, 2) gemm_bf(
    const bf16* __restrict__ Ah, const bf16* __restrict__ Al,
    const bf16* __restrict__ Bh, const bf16* __restrict__ Bl,
    float* __restrict__ C, const float* __restrict__ Add,
    bf16* __restrict__ CbH, bf16* __restrict__ CbL,
    int lda, int ldb, int ldc, int Kc,
    long sA1, long sA2, long sB1, long sB2, long sC1, long sC2, int nz2,
    int addDiv, int ldadd, long sAdd1)
{
    constexpr int WN   = BN / 4;
    constexpr int NSUB = BN / 32;
    constexpr int NBOP = BN / 64;        // B cp.async iterations per array
    constexpr int ABY  = 128 * 80;       // bytes of one A tile (128 rows x 40 bf16)
    constexpr int BBY  = BN * 80;
    constexpr int STG  = 2 * ABY + 2 * BBY;

    extern __shared__ __align__(16) char sm[];
    const int t = threadIdx.x, wid = t >> 5, lane = t & 31;
    const int g = lane >> 2, tq = lane & 3;
    const int wm = wid & 1, wn = wid >> 1;

    const int z = blockIdx.z, z1 = z / nz2, z2 = z - z1 * nz2;
    const long m0 = (long)blockIdx.y * 128, n0 = (long)blockIdx.x * BN;
    const bf16* Agh = Ah + z1 * sA1 + z2 * sA2 + m0 * lda;
    const bf16* Agl = Al + z1 * sA1 + z2 * sA2 + m0 * lda;
    const bf16* Bgh = Bh + z1 * sB1 + z2 * sB2 + n0 * ldb;
    const bf16* Bgl = Bl + z1 * sB1 + z2 * sB2 + n0 * ldb;

    const uint32_t smb = s2u(sm);
    const int crow = t >> 2, cseg = t & 3;   // copy coords: 16B seg per thread

    float acc[4][NSUB][4];
#pragma unroll
    for (int mi = 0; mi < 4; mi++)
#pragma unroll
        for (int ni = 0; ni < NSUB; ni++)
#pragma unroll
            for (int j = 0; j < 4; j++) acc[mi][ni][j] = 0.f;

    const int nch = Kc >> 5;

    // ---- prologue: async-load chunk 0 ----
    {
        const uint32_t st = smb;
#pragma unroll
        for (int i = 0; i < 2; i++) {
            int row = crow + i * 64;
            uint32_t d = st + row * 80 + cseg * 16;
            CPA(d,       Agh + (long)row * lda + cseg * 8);
            CPA(d + ABY, Agl + (long)row * lda + cseg * 8);
        }
#pragma unroll
        for (int i = 0; i < NBOP; i++) {
            int row = crow + i * 64;
            uint32_t d = st + 2 * ABY + row * 80 + cseg * 16;
            CPA(d,       Bgh + (long)row * ldb + cseg * 8);
            CPA(d + BBY, Bgl + (long)row * ldb + cseg * 8);
        }
        CPC();
    }

    const int aoff = (wm * 64 + g) * 80 + tq * 4;
    const int boff = (wn * WN + g) * 80 + tq * 4;

    for (int ch = 0; ch < nch; ch++) {
        if (ch + 1 < nch) {
            const uint32_t st = smb + ((ch + 1) & 1) * STG;
            const bf16* ah = Agh + (ch + 1) * 32;
            const bf16* al = Agl + (ch + 1) * 32;
            const bf16* bh = Bgh + (ch + 1) * 32;
            const bf16* bl = Bgl + (ch + 1) * 32;
#pragma unroll
            for (int i = 0; i < 2; i++) {
                int row = crow + i * 64;
                uint32_t d = st + row * 80 + cseg * 16;
                CPA(d,       ah + (long)row * lda + cseg * 8);
                CPA(d + ABY, al + (long)row * lda + cseg * 8);
            }
#pragma unroll
            for (int i = 0; i < NBOP; i++) {
                int row = crow + i * 64;
                uint32_t d = st + 2 * ABY + row * 80 + cseg * 16;
                CPA(d,       bh + (long)row * ldb + cseg * 8);
                CPA(d + BBY, bl + (long)row * ldb + cseg * 8);
            }
            CPC();
            CPW(1);
        } else {
            CPW(0);
        }
        __syncthreads();

        const char* sA = sm + (ch & 1) * STG;
        const char* sB = sA + 2 * ABY;
#pragma unroll
        for (int ks = 0; ks < 2; ks++) {
            const int ko = ks * 32;
            uint32_t fa[16], fbh[2 * NSUB], fbl[2 * NSUB];
#pragma unroll
            for (int mi = 0; mi < 4; mi++) {
                const char* p = sA + aoff + ko + mi * 1280;
                fa[mi * 4 + 0] = *(const uint32_t*)(p);
                fa[mi * 4 + 1] = *(const uint32_t*)(p + 640);
                fa[mi * 4 + 2] = *(const uint32_t*)(p + 16);
                fa[mi * 4 + 3] = *(const uint32_t*)(p + 656);
            }
#pragma unroll
            for (int ni = 0; ni < NSUB; ni++) {
                const char* p = sB + boff + ko + ni * 640;
                fbh[ni * 2] = *(const uint32_t*)p;
                fbh[ni * 2 + 1] = *(const uint32_t*)(p + 16);
            }
#pragma unroll
            for (int mi = 0; mi < 4; mi++)
#pragma unroll
                for (int ni = 0; ni < NSUB; ni++)
                    mma_bf16(acc[mi][ni], &fa[mi * 4], &fbh[ni * 2]);   // hi*hi
#pragma unroll
            for (int ni = 0; ni < NSUB; ni++) {
                const char* p = sB + BBY + boff + ko + ni * 640;
                fbl[ni * 2] = *(const uint32_t*)p;
                fbl[ni * 2 + 1] = *(const uint32_t*)(p + 16);
            }
#pragma unroll
            for (int mi = 0; mi < 4; mi++)
#pragma unroll
                for (int ni = 0; ni < NSUB; ni++)
                    mma_bf16(acc[mi][ni], &fa[mi * 4], &fbl[ni * 2]);   // hi*lo
#pragma unroll
            for (int mi = 0; mi < 4; mi++) {
                const char* p = sA + ABY + aoff + ko + mi * 1280;
                fa[mi * 4 + 0] = *(const uint32_t*)(p);
                fa[mi * 4 + 1] = *(const uint32_t*)(p + 640);
                fa[mi * 4 + 2] = *(const uint32_t*)(p + 16);
                fa[mi * 4 + 3] = *(const uint32_t*)(p + 656);
            }
#pragma unroll
            for (int mi = 0; mi < 4; mi++)
#pragma unroll
                for (int ni = 0; ni < NSUB; ni++)
                    mma_bf16(acc[mi][ni], &fa[mi * 4], &fbh[ni * 2]);   // lo*hi
        }
        __syncthreads();
    }

    // ---- epilogue ----
    float* Cp = C ? (C + z1 * sC1 + z2 * sC2) : (float*)0;
    bf16* Ch = CbH ? (CbH + z1 * sC1 + z2 * sC2) : (bf16*)0;
    bf16* Cl = CbL ? (CbL + z1 * sC1 + z2 * sC2) : (bf16*)0;
    const float* Ad = Add ? (Add + z1 * sAdd1) : (const float*)0;
#pragma unroll
    for (int mi = 0; mi < 4; mi++) {
        long r0 = m0 + wm * 64 + mi * 16 + g;
#pragma unroll
        for (int ni = 0; ni < NSUB; ni++) {
            long col = n0 + wn * WN + ni * 8 + tq * 2;
            float2 v0 = make_float2(acc[mi][ni][0], acc[mi][ni][1]);
            float2 v1 = make_float2(acc[mi][ni][2], acc[mi][ni][3]);
            if (Ad) {
                float2 a0 = *(const float2*)(Ad + (r0 / addDiv) * (long)ldadd + col);
                float2 a1 = *(const float2*)(Ad + ((r0 + 8) / addDiv) * (long)ldadd + col);
                v0.x += a0.x; v0.y += a0.y; v1.x += a1.x; v1.y += a1.y;
            }
            if (Cp) {
                *(float2*)(Cp + r0 * ldc + col) = v0;
                *(float2*)(Cp + (r0 + 8) * ldc + col) = v1;
            }
            if (Ch) {
                long i0 = r0 * ldc + col, i1 = (r0 + 8) * ldc + col;
                bf16 h0 = __float2bfloat16_rn(v0.x), h1 = __float2bfloat16_rn(v0.y);
                bf16 h2 = __float2bfloat16_rn(v1.x), h3 = __float2bfloat16_rn(v1.y);
                *(__nv_bfloat162*)(Ch + i0) = __nv_bfloat162(h0, h1);
                *(__nv_bfloat162*)(Ch + i1) = __nv_bfloat162(h2, h3);
                *(__nv_bfloat162*)(Cl + i0) = __nv_bfloat162(
                    __float2bfloat16_rn(v0.x - __bfloat162float(h0)),
                    __float2bfloat16_rn(v0.y - __bfloat162float(h1)));
                *(__nv_bfloat162*)(Cl + i1) = __nv_bfloat162(
                    __float2bfloat16_rn(v1.x - __bfloat162float(h2)),
                    __float2bfloat16_rn(v1.y - __bfloat162float(h3)));
            }
        }
    }
}

// ---------------- input transpose + bf16 split ----------------
__global__ void k_split_in(const float* __restrict__ tgt, const float* __restrict__ mem)
{
    long stride = (long)gridDim.x * blockDim.x;
    long base   = (long)blockIdx.x * blockDim.x + threadIdx.x;
    const long TT = (long)C_N * C_D * 3;
    for (long i = base; i < TT; i += stride) {
        int  x  = (int)(i % 3);
        long nc = i / 3;
        bsplit(tgt[i], &g_Tb_h[x][0][0], &g_Tb_l[x][0][0], nc);
    }
    const long TMm = (long)C_E * C_D * 3;
    for (long i = base; i < TMm; i += stride) {
        int  x  = (int)(i % 3);
        long ec = i / 3;
        bsplit(mem[i], &g_Mb_h[x][0][0], &g_Mb_l[x][0][0], ec);
    }
}

// ---------------- weight splits ----------------
__global__ void k_split(const float* __restrict__ s, bf16* __restrict__ H, bf16* __restrict__ L)
{
    long i = (long)blockIdx.x * 256 + threadIdx.x;
    bsplit(s[i], H, L, i);
}
__global__ void k_split_t(const float* __restrict__ wa)   // 512x64 -> 64x512
{
    int i = blockIdx.x * 256 + threadIdx.x;   // i < 32768
    int r = i >> 6, c = i & 63;
    bsplit(wa[i], g_Wa_h, g_Wa_l, (long)c * C_D + r);
}

// ---------------- fused edge MLP ----------------
__global__ void __launch_bounds__(256) k_mlp(
    const float* __restrict__ es, const float* __restrict__ w1, const float* __restrict__ b1,
    const float* __restrict__ w2, const float* __restrict__ b2,
    const float* __restrict__ w3, const float* __restrict__ b3)
{
    __shared__ float s_es[64][65];
    __shared__ float s_w1[64][32];
    __shared__ float s_w2[32][32];
    __shared__ float s_h1[64][33];
    __shared__ float s_h2[64][33];
    const int t = threadIdx.x;
    const long e0 = (long)blockIdx.x * 64;

    for (int i = t; i < 64 * 32; i += 256) s_w1[i >> 5][i & 31] = w1[i];
    for (int i = t; i < 32 * 32; i += 256) s_w2[i >> 5][i & 31] = w2[i];
    for (int i = t; i < 64 * 64; i += 256) s_es[i >> 6][i & 63] = es[e0 * 64 + i];
    __syncthreads();

    for (int i = t; i < 64 * 32; i += 256) {
        int e = i >> 5, j = i & 31;
        float acc = b1[j];
#pragma unroll 8
        for (int c = 0; c < 64; c++) acc = fmaf(s_es[e][c], s_w1[c][j], acc);
        s_h1[e][j] = acc / (1.f + expf(-acc));
    }
    __syncthreads();
    for (int i = t; i < 64 * 32; i += 256) {
        int e = i >> 5, j = i & 31;
        float acc = b2[j];
#pragma unroll 8
        for (int c = 0; c < 32; c++) acc = fmaf(s_h1[e][c], s_w2[c][j], acc);
        s_h2[e][j] = acc / (1.f + expf(-acc));
    }
    __syncthreads();
    for (int i = t; i < 64 * 1536; i += 256) {
        int e = i / 1536, o = i - e * 1536;
        float acc = b3[o];
#pragma unroll 8
        for (int c = 0; c < 32; c++) acc = fmaf(s_h2[e][c], w3[c * 1536 + o], acc);
        g_w[e0 + e][o] = acc;
    }
}

// ---------------- pointwise equivariant products ----------------
__global__ void k_pointwise(const float* __restrict__ esh)
{
    long stride = (long)gridDim.x * blockDim.x;
    for (long i = (long)blockIdx.x * blockDim.x + threadIdx.x; i < (long)C_E * C_D; i += stride) {
        int  c = (int)(i & 511);
        long e = i >> 9;
        float s  = esh[e * 4 + 0];
        float v0 = esh[e * 4 + 1], v1 = esh[e * 4 + 2], v2 = esh[e * 4 + 3];
        float m0 = g_MSG[0][e][c], m1 = g_MSG[1][e][c], m2 = g_MSG[2][e][c];
        float w0v = g_w[e][c], w1v = g_w[e][512 + c], w2v = g_w[e][1024 + c];
        float psc = w0v * (m0 * v0 + m1 * v1 + m2 * v2) * 0.5773502691896258f;
        bsplit(psc, &g_pscb_h[0][0], &g_pscb_l[0][0], i);
        float k2 = w2v * 0.7071067811865475f;
        float ws = w1v * s;
        g_PV[0][e][c] = ws * m0 + k2 * (m1 * v2 - m2 * v1);
        g_PV[1][e][c] = ws * m1 + k2 * (m2 * v0 - m0 * v2);
        g_PV[2][e][c] = ws * m2 + k2 * (m0 * v1 - m1 * v0);
    }
}

// ---------------- alpha post: LN + smooth_lrelu + head dot ----------------
__global__ void k_alpha_post(const float* __restrict__ gg, const float* __restrict__ bb,
                             const float* __restrict__ adot)
{
    int gt = blockIdx.x * blockDim.x + threadIdx.x;
    int e = gt >> 5, lane = gt & 31;
    if (e >= C_E) return;
    float v0 = g_araw[e][lane * 2], v1 = g_araw[e][lane * 2 + 1];
    float s = v0 + v1, s2 = v0 * v0 + v1 * v1;
#pragma unroll
    for (int o = 16; o > 0; o >>= 1) {
        s  += __shfl_xor_sync(0xffffffffu, s, o);
        s2 += __shfl_xor_sync(0xffffffffu, s2, o);
    }
    float mu  = s * (1.f / 64.f);
    float var = s2 * (1.f / 64.f) - mu * mu;
    float inv = rsqrtf(var + C_EPS);
    float a0 = (v0 - mu) * inv * gg[lane * 2]     + bb[lane * 2];
    float a1 = (v1 - mu) * inv * gg[lane * 2 + 1] + bb[lane * 2 + 1];
    a0 = 0.6f * a0 + 0.4f * a0 * tanhf(0.5f * a0);
    a1 = 0.6f * a1 + 0.4f * a1 * tanhf(0.5f * a1);
    int h = lane >> 2;
    int m = (lane & 3) * 2;
    float p = a0 * adot[h * 8 + m] + a1 * adot[h * 8 + m + 1];
    p += __shfl_xor_sync(0xffffffffu, p, 1);
    p += __shfl_xor_sync(0xffffffffu, p, 2);
    if ((lane & 3) == 0) g_attr[e][h] = p;
}

// ---------------- softmax over K per (n,h) ----------------
__global__ void k_softmax()
{
    int i = blockIdx.x * blockDim.x + threadIdx.x;
    if (i >= C_N * C_H) return;
    int n = i >> 3, h = i & 7;
    float v[16]; float mx = -1e30f;
#pragma unroll
    for (int k = 0; k < 16; k++) { v[k] = g_attr[n * 16 + k][h]; mx = fmaxf(mx, v[k]); }
    float sum = 0.f;
#pragma unroll
    for (int k = 0; k < 16; k++) { v[k] = expf(v[k] - mx); sum += v[k]; }
    float is = 1.f / sum;
#pragma unroll
    for (int k = 0; k < 16; k++) g_att[n * 16 + k][h] = v[k] * is;
}

// ---------------- z = sum_k att * pv (bf16-pair output) ----------------
__global__ void __launch_bounds__(256) k_z()
{
    int n = blockIdx.x, x = blockIdx.y;
    __shared__ float s_a[16][8];
    if (threadIdx.x < 128)
        s_a[threadIdx.x >> 3][threadIdx.x & 7] = g_att[n * 16 + (threadIdx.x >> 3)][threadIdx.x & 7];
    __syncthreads();
    for (int c = threadIdx.x; c < C_D; c += 256) {
        float acc[8] = {0, 0, 0, 0, 0, 0, 0, 0};
#pragma unroll
        for (int k = 0; k < 16; k++) {
            float pv = g_PV[x][n * 16 + k][c];
#pragma unroll
            for (int h = 0; h < 8; h++) acc[h] = fmaf(s_a[k][h], pv, acc[h]);
        }
#pragma unroll
        for (int h = 0; h < 8; h++) {
            long idx = (((long)x * C_N + n) * C_H + h) * C_D + c;
            bsplit(acc[h], &g_Zb_h[0][0][0][0], &g_Zb_l[0][0][0][0], idx);
        }
    }
}

// ---------------- vector-norm LayerNorm (vn_ln) ----------------
__global__ void __launch_bounds__(256) k_vnln(const float* __restrict__ Xin, float* __restrict__ Xout,
                                              bf16* __restrict__ bH, bf16* __restrict__ bL,
                                              const float* __restrict__ gg, const float* __restrict__ bb,
                                              int inter)
{
    int n = blockIdx.x, t = threadIdx.x;
    const long P = (long)C_N * C_D;
    __shared__ float rs[8], rs2[8];
    __shared__ float smu, sinv;
    float xv[2][3], nc[2];
    float s = 0.f, s2 = 0.f;
#pragma unroll
    for (int i = 0; i < 2; i++) {
        int c = t + i * 256;
#pragma unroll
        for (int xx = 0; xx < 3; xx++) xv[i][xx] = Xin[xx * P + (long)n * C_D + c];
        float v = sqrtf(xv[i][0] * xv[i][0] + xv[i][1] * xv[i][1] + xv[i][2] * xv[i][2] + C_EPS);
        nc[i] = v; s += v; s2 = fmaf(v, v, s2);
    }
#pragma unroll
    for (int o = 16; o > 0; o >>= 1) {
        s  += __shfl_xor_sync(0xffffffffu, s, o);
        s2 += __shfl_xor_sync(0xffffffffu, s2, o);
    }
    if ((t & 31) == 0) { rs[t >> 5] = s; rs2[t >> 5] = s2; }
    __syncthreads();
    if (t == 0) {
        float S = 0.f, S2 = 0.f;
        for (int i = 0; i < 8; i++) { S += rs[i]; S2 += rs2[i]; }
        float mu  = S * (1.f / 512.f);
        float var = S2 * (1.f / 512.f) - mu * mu;
        smu = mu; sinv = rsqrtf(var + C_EPS);
    }
    __syncthreads();
#pragma unroll
    for (int i = 0; i < 2; i++) {
        int c = t + i * 256;
        float ln = (nc[i] - smu) * sinv * gg[c] + bb[c];
        float sc = ln / nc[i];
        if (inter) {
#pragma unroll
            for (int xx = 0; xx < 3; xx++) Xout[(long)n * 1536 + c * 3 + xx] = xv[i][xx] * sc;
        } else {
#pragma unroll
            for (int xx = 0; xx < 3; xx++) {
                long idx = xx * P + (long)n * C_D + c;
                float v = xv[i][xx] * sc;
                Xout[idx] = v;
                if (bH) bsplit(v, bH, bL, idx);
            }
        }
    }
}

// ---------------- FF gating (projection rejection) ----------------
__global__ void k_gate()
{
    const long P = (long)C_N * C_FF;
    const float* Y  = &g_Y[0][0][0];
    const float* Dv = &g_DV[0][0][0];
    long stride = (long)gridDim.x * blockDim.x;
    for (long i = (long)blockIdx.x * blockDim.x + threadIdx.x; i < P; i += stride) {
        float y0 = Y[i], y1 = Y[P + i], y2 = Y[2 * P + i];
        float d0 = Dv[i], d1 = Dv[P + i], d2 = Dv[2 * P + i];
        float dot = y0 * d0 + y1 * d1 + y2 * d2;
        float dnn = d0 * d0 + d1 * d1 + d2 * d2 + C_EPS;
        float f = (dot >= 0.f) ? 0.f : 0.8f * dot / dnn;
        bsplit(y0 - f * d0, &g_Y2b_h[0][0][0], &g_Y2b_l[0][0][0], i);
        bsplit(y1 - f * d1, &g_Y2b_h[0][0][0], &g_Y2b_l[0][0][0], P + i);
        bsplit(y2 - f * d2, &g_Y2b_h[0][0][0], &g_Y2b_l[0][0][0], 2 * P + i);
    }
}

// ---------------- host launch ----------------
extern "C" void kernel_launch(void* const* d_in, const int* in_sizes, int n_in,
                              void* d_out, int out_size)
{
    const float* tgt    = (const float*)d_in[0];
    const float* mem    = (const float*)d_in[1];
    const float* esh    = (const float*)d_in[2];
    const float* escal  = (const float*)d_in[3];
    const float* W_src  = (const float*)d_in[4];
    const float* W_dst  = (const float*)d_in[5];
    const float* fc_w1  = (const float*)d_in[6];
    const float* fc_b1  = (const float*)d_in[7];
    const float* fc_w2  = (const float*)d_in[8];
    const float* fc_b2  = (const float*)d_in[9];
    const float* fc_w3  = (const float*)d_in[10];
    const float* fc_b3  = (const float*)d_in[11];
    const float* W_alpha= (const float*)d_in[12];
    const float* ln_a_g = (const float*)d_in[13];
    const float* ln_a_b = (const float*)d_in[14];
    const float* adot   = (const float*)d_in[15];
    const float* W_value= (const float*)d_in[16];
    const float* W_proj = (const float*)d_in[17];
    const float* n1_g   = (const float*)d_in[18];
    const float* n1_b   = (const float*)d_in[19];
    const float* n2_g   = (const float*)d_in[20];
    const float* n2_b   = (const float*)d_in[21];
    const float* W_ff1  = (const float*)d_in[22];
    const float* W_ffd  = (const float*)d_in[23];
    const float* W_ff2  = (const float*)d_in[24];

#define SYM(p, s) cudaGetSymbolAddress((void**)&p, s)
    float *pTV, *pMSG, *paraw, *pXP, *pX1, *pY, *pDV, *pY3;
    SYM(pTV, g_TV); SYM(pMSG, g_MSG); SYM(paraw, g_araw);
    SYM(pXP, g_XP); SYM(pX1, g_X1); SYM(pY, g_Y); SYM(pDV, g_DV); SYM(pY3, g_Y3);
    bf16 *pTbh, *pTbl, *pMbh, *pMbl, *ppsh, *ppsl, *pZh, *pZl, *pOh, *pOl;
    bf16 *pX1h, *pX1l, *pYh, *pYl, *pY2h, *pY2l;
    SYM(pTbh, g_Tb_h); SYM(pTbl, g_Tb_l); SYM(pMbh, g_Mb_h); SYM(pMbl, g_Mb_l);
    SYM(ppsh, g_pscb_h); SYM(ppsl, g_pscb_l); SYM(pZh, g_Zb_h); SYM(pZl, g_Zb_l);
    SYM(pOh, g_OUTb_h); SYM(pOl, g_OUTb_l); SYM(pX1h, g_X1b_h); SYM(pX1l, g_X1b_l);
    SYM(pYh, g_Yb_h); SYM(pYl, g_Yb_l); SYM(pY2h, g_Y2b_h); SYM(pY2l, g_Y2b_l);
    bf16 *pWsh, *pWsl, *pWdh, *pWdl, *pWah, *pWal, *pWvh, *pWvl, *pWph, *pWpl;
    bf16 *pW1h, *pW1l, *pWfh, *pWfl, *pW2h, *pW2l;
    SYM(pWsh, g_Wsrc_h); SYM(pWsl, g_Wsrc_l); SYM(pWdh, g_Wdst_h); SYM(pWdl, g_Wdst_l);
    SYM(pWah, g_Wa_h); SYM(pWal, g_Wa_l); SYM(pWvh, g_Wv_h); SYM(pWvl, g_Wv_l);
    SYM(pWph, g_Wp_h); SYM(pWpl, g_Wp_l); SYM(pW1h, g_Wf1_h); SYM(pW1l, g_Wf1_l);
    SYM(pWfh, g_Wfd_h); SYM(pWfl, g_Wfd_l); SYM(pW2h, g_Wf2_h); SYM(pW2l, g_Wf2_l);
#undef SYM

    const long NP_D  = (long)C_N * C_D;
    const long EP_D  = (long)C_E * C_D;
    const long NP_FF = (long)C_N * C_FF;
    const long NHD   = (long)C_N * C_H * C_D;

    const int SM128 = 2 * (2 * 128 * 80 + 2 * 128 * 80);  // 81920
    const int SM64  = 2 * (2 * 128 * 80 + 2 * 64 * 80);   // 61440
    cudaFuncSetAttribute(gemm_bf<128>, cudaFuncAttributeMaxDynamicSharedMemorySize, SM128);
    cudaFuncSetAttribute(gemm_bf<64>,  cudaFuncAttributeMaxDynamicSharedMemorySize, SM64);

    // 1) input + weight splits
    k_split_in<<<4096, 256>>>(tgt, mem);
    k_split<<<C_D*C_D/256, 256>>>(W_src, pWsh, pWsl);
    k_split<<<C_D*C_D/256, 256>>>(W_dst, pWdh, pWdl);
    k_split<<<C_D*C_D/256, 256>>>(W_value, pWvh, pWvl);
    k_split<<<C_D*C_D/256, 256>>>(W_proj, pWph, pWpl);
    k_split<<<C_FF*C_D/256, 256>>>(W_ff1, pW1h, pW1l);
    k_split<<<C_FF*C_FF/256, 256>>>(W_ffd, pWfh, pWfl);
    k_split<<<C_D*C_FF/256, 256>>>(W_ff2, pW2h, pW2l);
    k_split_t<<<C_D*C_MA/256, 256>>>(W_alpha);

    // 2) tv = W_dst @ tgt
    gemm_bf<128><<<dim3(4, 8, 3), 256, SM128>>>(pTbh, pTbl, pWdh, pWdl, pTV, nullptr, nullptr, nullptr,
        C_D, C_D, C_D, C_D, NP_D, 0, 0, 0, NP_D, 0, 1, 1, 0, 0);

    // 3) msg = W_src @ memory + tv[e/K]
    gemm_bf<128><<<dim3(4, 128, 3), 256, SM128>>>(pMbh, pMbl, pWsh, pWsl, pMSG, pTV, nullptr, nullptr,
        C_D, C_D, C_D, C_D, EP_D, 0, 0, 0, EP_D, 0, 1, C_K, C_D, NP_D);

    // 4) edge MLP -> g_w
    k_mlp<<<C_E / 64, 256>>>(escal, fc_w1, fc_b1, fc_w2, fc_b2, fc_w3, fc_b3);

    // 5) p_sc / pv
    k_pointwise<<<2048, 256>>>(esh);

    // 6) a_raw = p_sc @ W_alpha
    gemm_bf<64><<<dim3(1, 128, 1), 256, SM64>>>(ppsh, ppsl, pWah, pWal, paraw, nullptr, nullptr, nullptr,
        C_D, C_D, C_MA, C_D, 0, 0, 0, 0, 0, 0, 1, 1, 0, 0);

    // 7) LN + lrelu + head dot, then softmax over K
    k_alpha_post<<<2048, 256>>>(ln_a_g, ln_a_b, adot);
    k_softmax<<<32, 256>>>();

    // 8) z = sum_k att * pv
    k_z<<<dim3(C_N, 3), 256>>>();

    // 9) out = W_value @ z (per head, bf16 out), then proj + tv
    gemm_bf<64><<<dim3(1, 8, 24), 256, SM64>>>(pZh, pZl, pWvh, pWvl, nullptr, nullptr, pOh, pOl,
        C_H * C_D, C_D, C_D, C_D, NHD, C_D, 0, 64 * C_D, NP_D, 64, C_H, 1, 0, 0);
    gemm_bf<128><<<dim3(4, 8, 3), 256, SM128>>>(pOh, pOl, pWph, pWpl, pXP, pTV, nullptr, nullptr,
        C_D, C_D, C_D, C_D, NP_D, 0, 0, 0, NP_D, 0, 1, 1, C_D, NP_D);

    // 10) vn_ln #1 (fp32 + bf16 pair)
    k_vnln<<<C_N, 256>>>(pXP, pX1, pX1h, pX1l, n1_g, n1_b, 0);

    // 11) FF block
    gemm_bf<128><<<dim3(16, 8, 3), 256, SM128>>>(pX1h, pX1l, pW1h, pW1l, pY, nullptr, pYh, pYl,
        C_D, C_D, C_FF, C_D, NP_D, 0, 0, 0, NP_FF, 0, 1, 1, 0, 0);
    gemm_bf<128><<<dim3(16, 8, 3), 256, SM128>>>(pYh, pYl, pWfh, pWfl, pDV, nullptr, nullptr, nullptr,
        C_FF, C_FF, C_FF, C_FF, NP_FF, 0, 0, 0, NP_FF, 0, 1, 1, 0, 0);
    k_gate<<<2048, 256>>>();
    gemm_bf<128><<<dim3(4, 8, 3), 256, SM128>>>(pY2h, pY2l, pW2h, pW2l, pY3, pX1, nullptr, nullptr,
        C_FF, C_FF, C_D, C_FF, NP_FF, 0, 0, 0, NP_D, 0, 1, 1, C_D, NP_D);

    // 12) vn_ln #2 -> interleaved (n, c*3+x) output
    k_vnln<<<C_N, 256>>>(pY3, (float*)d_out, nullptr, nullptr, n2_g, n2_b, 1);
}